// round 15
// baseline (speedup 1.0000x reference)
#include <cuda_runtime.h>
#include <cuda_bf16.h>
#include <cstdint>

// Problem constants
#define Bsz 2
#define Sq  2048
#define Hh  2048
#define NHd 16
#define HDd 128

static const int M_ROWS = Bsz * Sq;    // 4096
static const int QKV_N  = 3 * Hh;      // 6144

// ---------------- scratch (device globals; no allocation allowed) -----------
__device__ float g_qkv[4096 * 6144];           // [b*S+s][3H]
__device__ float g_q[Bsz * NHd * Sq * HDd];    // [bh][s][d]
__device__ float g_k[Bsz * NHd * Sq * HDd];
__device__ float g_v[Bsz * NHd * Sq * HDd];
__device__ float g_attn[4096 * 2048];          // [b*S+s][H]

// bf16 hi/lo split buffers
__device__ __nv_bfloat16 g_hhi[4096 * 2048], g_hlo[4096 * 2048];
__device__ __nv_bfloat16 g_wqhi[6144 * 2048], g_wqlo[6144 * 2048];
__device__ __nv_bfloat16 g_ahi[4096 * 2048], g_alo[4096 * 2048];
__device__ __nv_bfloat16 g_wohi[2048 * 2048], g_wolo[2048 * 2048];

// ---------------- warp-MMA helpers (compute_103-safe) -----------------------
__device__ __forceinline__ uint32_t smem_u32(const void* p) {
    uint32_t a;
    asm("{ .reg .u64 t; cvta.to.shared.u64 t, %1; cvt.u32.u64 %0, t; }" : "=r"(a) : "l"(p));
    return a;
}
__device__ __forceinline__ void ldm_x4(uint32_t* r, uint32_t addr) {
    asm volatile("ldmatrix.sync.aligned.m8n8.x4.shared.b16 {%0,%1,%2,%3}, [%4];"
                 : "=r"(r[0]), "=r"(r[1]), "=r"(r[2]), "=r"(r[3]) : "r"(addr));
}
__device__ __forceinline__ void ldm_x2(uint32_t* r, uint32_t addr) {
    asm volatile("ldmatrix.sync.aligned.m8n8.x2.shared.b16 {%0,%1}, [%2];"
                 : "=r"(r[0]), "=r"(r[1]) : "r"(addr));
}
__device__ __forceinline__ void mma16816(float* d, const uint32_t* a, const uint32_t* b) {
    asm volatile("mma.sync.aligned.m16n8k16.row.col.f32.bf16.bf16.f32 "
                 "{%0,%1,%2,%3}, {%4,%5,%6,%7}, {%8,%9}, {%0,%1,%2,%3};"
                 : "+f"(d[0]), "+f"(d[1]), "+f"(d[2]), "+f"(d[3])
                 : "r"(a[0]), "r"(a[1]), "r"(a[2]), "r"(a[3]), "r"(b[0]), "r"(b[1]));
}

// ============================================================================
// fp32 -> bf16 hi/lo split (vectorized x4)
// ============================================================================
__global__ __launch_bounds__(256)
void split_hilo(const float* __restrict__ x, __nv_bfloat16* __restrict__ hi,
                __nv_bfloat16* __restrict__ lo, int n4) {
    int i = blockIdx.x * 256 + threadIdx.x;
    if (i >= n4) return;
    float4 v = ((const float4*)x)[i];
    __nv_bfloat16 h0 = __float2bfloat16(v.x);
    __nv_bfloat16 h1 = __float2bfloat16(v.y);
    __nv_bfloat16 h2 = __float2bfloat16(v.z);
    __nv_bfloat16 h3 = __float2bfloat16(v.w);
    ushort4 H, L;
    H.x = __bfloat16_as_ushort(h0); H.y = __bfloat16_as_ushort(h1);
    H.z = __bfloat16_as_ushort(h2); H.w = __bfloat16_as_ushort(h3);
    L.x = __bfloat16_as_ushort(__float2bfloat16(v.x - __bfloat162float(h0)));
    L.y = __bfloat16_as_ushort(__float2bfloat16(v.y - __bfloat162float(h1)));
    L.z = __bfloat16_as_ushort(__float2bfloat16(v.z - __bfloat162float(h2)));
    L.w = __bfloat16_as_ushort(__float2bfloat16(v.w - __bfloat162float(h3)));
    ((ushort4*)hi)[i] = H;
    ((ushort4*)lo)[i] = L;
}

// ============================================================================
// HMMA bf16x3 GEMM (NT): C[m][n] = sum_k A[m][k]*B[n][k], fp32 out.
// CTA tile 128x128, BK=32 bf16. 8 warps in 2(m) x 4(n); warp tile 64x32.
// smem: 4 tiles [128 rows][pitch 40 bf16] (Ahi, Alo, Bhi, Blo) = 40960 B.
// ============================================================================
#define GPITCH 40

__global__ __launch_bounds__(256, 2)
void gemm_mma(const __nv_bfloat16* __restrict__ Ahi, const __nv_bfloat16* __restrict__ Alo,
              const __nv_bfloat16* __restrict__ Bhi, const __nv_bfloat16* __restrict__ Blo,
              float* __restrict__ C, int M, int N, int K) {
    __shared__ __nv_bfloat16 sm[4 * 128 * GPITCH];
    __nv_bfloat16* sAhi = sm;
    __nv_bfloat16* sAlo = sm + 128 * GPITCH;
    __nv_bfloat16* sBhi = sm + 2 * 128 * GPITCH;
    __nv_bfloat16* sBlo = sm + 3 * 128 * GPITCH;

    const int tid  = threadIdx.x;
    const int wid  = tid >> 5;
    const int lane = tid & 31;
    const int warp_m = wid & 1;    // 0..1  (64 rows each)
    const int warp_n = wid >> 1;   // 0..3  (32 cols each)
    const int m0 = blockIdx.y * 128;
    const int n0 = blockIdx.x * 128;

    const __nv_bfloat16* a_hi = Ahi + (size_t)m0 * K;
    const __nv_bfloat16* a_lo = Alo + (size_t)m0 * K;
    const __nv_bfloat16* b_hi = Bhi + (size_t)n0 * K;
    const __nv_bfloat16* b_lo = Blo + (size_t)n0 * K;

    // gmem->smem mapping: 2 iters x 256 threads cover 128 rows x 4 segs of 16B
    const int ldrow0 = tid >> 2;          // 0..63
    const int ldseg  = tid & 3;           // 16B segment (8 bf16)

    // ldmatrix base addresses (element offsets within a tile)
    // A: row = warp_m*64 + mi*16 + (lane&15), col = (lane>>4)*8 (+ kstep*16)
    const uint32_t aoff = ((warp_m * 64 + (lane & 15)) * GPITCH + (lane >> 4) * 8) * 2;
    // B: row = warp_n*32 + ni*8 + (lane&7), col = ((lane>>3)&1)*8 (+ kstep*16)
    const uint32_t boff = ((warp_n * 32 + (lane & 7)) * GPITCH + ((lane >> 3) & 1) * 8) * 2;

    const uint32_t sAhi_b = smem_u32(sAhi), sAlo_b = smem_u32(sAlo);
    const uint32_t sBhi_b = smem_u32(sBhi), sBlo_b = smem_u32(sBlo);

    float acc[4][4][4];
#pragma unroll
    for (int i = 0; i < 4; i++)
#pragma unroll
        for (int j = 0; j < 4; j++)
#pragma unroll
            for (int q = 0; q < 4; q++) acc[i][j][q] = 0.f;

    const int nchunk = K >> 5;   // K/32
    for (int c = 0; c < nchunk; c++) {
        const int kg = c * 32 + ldseg * 8;
        // fill smem (each thread: 2 rows x 4 tiles)
#pragma unroll
        for (int h = 0; h < 2; h++) {
            int r = ldrow0 + h * 64;
            size_t go = (size_t)r * K + kg;
            uint32_t so = (uint32_t)(r * GPITCH + ldseg * 8) * 2;
            *(uint4*)((char*)sAhi + so) = *(const uint4*)(a_hi + go);
            *(uint4*)((char*)sAlo + so) = *(const uint4*)(a_lo + go);
            *(uint4*)((char*)sBhi + so) = *(const uint4*)(b_hi + go);
            *(uint4*)((char*)sBlo + so) = *(const uint4*)(b_lo + go);
        }
        __syncthreads();

#pragma unroll
        for (int ks = 0; ks < 2; ks++) {
            const uint32_t kso = ks * 32;   // 16 elems * 2B
            uint32_t fahi[4][4], falo[4][4], fb[4][2];
            // A_hi, A_lo fragments
#pragma unroll
            for (int mi = 0; mi < 4; mi++) {
                uint32_t ao = aoff + (uint32_t)(mi * 16 * GPITCH) * 2 + kso;
                ldm_x4(fahi[mi], sAhi_b + ao);
                ldm_x4(falo[mi], sAlo_b + ao);
            }
            // B_hi: hi*hi and lo*hi
#pragma unroll
            for (int ni = 0; ni < 4; ni++) {
                uint32_t bo = boff + (uint32_t)(ni * 8 * GPITCH) * 2 + kso;
                ldm_x2(fb[ni], sBhi_b + bo);
            }
#pragma unroll
            for (int mi = 0; mi < 4; mi++)
#pragma unroll
                for (int ni = 0; ni < 4; ni++) {
                    mma16816(acc[mi][ni], fahi[mi], fb[ni]);
                    mma16816(acc[mi][ni], falo[mi], fb[ni]);
                }
            // B_lo: hi*lo
#pragma unroll
            for (int ni = 0; ni < 4; ni++) {
                uint32_t bo = boff + (uint32_t)(ni * 8 * GPITCH) * 2 + kso;
                ldm_x2(fb[ni], sBlo_b + bo);
            }
#pragma unroll
            for (int mi = 0; mi < 4; mi++)
#pragma unroll
                for (int ni = 0; ni < 4; ni++)
                    mma16816(acc[mi][ni], fahi[mi], fb[ni]);
        }
        __syncthreads();
    }

    // epilogue: lane l of each atom holds rows (l/4, l/4+8), cols (l%4)*2+{0,1}
    const int er = lane >> 2;
    const int ec = (lane & 3) * 2;
#pragma unroll
    for (int mi = 0; mi < 4; mi++) {
#pragma unroll
        for (int ni = 0; ni < 4; ni++) {
            int row = m0 + warp_m * 64 + mi * 16 + er;
            int col = n0 + warp_n * 32 + ni * 8 + ec;
            float* p0 = C + (size_t)row * N + col;
            float* p1 = C + (size_t)(row + 8) * N + col;
            p0[0] = acc[mi][ni][0]; p0[1] = acc[mi][ni][1];
            p1[0] = acc[mi][ni][2]; p1[1] = acc[mi][ni][3];
        }
    }
}

// ============================================================================
// RoPE + layout split: g_qkv [b,s,3,nh,d] -> g_q/g_k/g_v [bh][s][d]
// ============================================================================
__global__ __launch_bounds__(256)
void rope_split(const float* __restrict__ cosT, const float* __restrict__ sinT) {
    int idx = blockIdx.x * blockDim.x + threadIdx.x;
    int d  = idx & 127;
    int nh = (idx >> 7) & 15;
    int s  = (idx >> 11) & 2047;
    int b  = idx >> 22;

    size_t base = ((size_t)(b * Sq + s)) * (3 * Hh) + nh * HDd;
    int dp = (d < 64) ? d + 64 : d - 64;
    float c  = cosT[s * HDd + d];
    float sn = sinT[s * HDd + d];
    size_t o = (((size_t)(b * NHd + nh)) * Sq + s) * HDd + d;

    float x  = g_qkv[base + d];
    float xp = g_qkv[base + dp];
    float rot = (d < 64) ? -xp : xp;
    g_q[o] = x * c + rot * sn;
    x  = g_qkv[base + Hh + d];
    xp = g_qkv[base + Hh + dp];
    rot = (d < 64) ? -xp : xp;
    g_k[o] = x * c + rot * sn;
    g_v[o] = g_qkv[base + 2 * Hh + d];
}

// ============================================================================
// Flash attention (fp32), 64-row Q block per CTA, 64-col K/V tiles, causal.
// ============================================================================
#define FA_SMEM ((8192 + 8192 + 8192 + 64 * 65) * 4)

__global__ __launch_bounds__(256, 1)
void fattn() {
    extern __shared__ float sm[];
    float* Qs = sm;
    float* Ks = sm + 8192;
    float* Vs = sm + 16384;
    float* Ps = sm + 24576;

    const int bh = blockIdx.y;
    const int iq = 31 - blockIdx.x;
    const int tid = threadIdx.x;
    const int tx = tid & 15;
    const int ty = tid >> 4;

    const float* Qg = g_q + (size_t)bh * Sq * HDd;
    const float* Kg = g_k + (size_t)bh * Sq * HDd;
    const float* Vg = g_v + (size_t)bh * Sq * HDd;

    for (int x = tid; x < 64 * 32; x += 256) {
        int n  = x >> 5;
        int d4 = x & 31;
        float4 v = *(const float4*)(Qg + (size_t)(iq * 64 + n) * HDd + d4 * 4);
        int col = (n + d4 * 4) & 63;
        Qs[(d4 * 4 + 0) * 64 + col] = v.x;
        Qs[(d4 * 4 + 1) * 64 + col] = v.y;
        Qs[(d4 * 4 + 2) * 64 + col] = v.z;
        Qs[(d4 * 4 + 3) * 64 + col] = v.w;
    }

    float acc[4][8];
    float mrow[4], lrow[4];
#pragma unroll
    for (int i = 0; i < 4; i++) {
        mrow[i] = -1e30f;
        lrow[i] = 0.f;
#pragma unroll
        for (int j = 0; j < 8; j++) acc[i][j] = 0.f;
    }

    const float scale = 0.08838834764831845f;

    for (int jt = 0; jt <= iq; jt++) {
        __syncthreads();
        const int kbase = jt * 64;
        for (int x = tid; x < 64 * 32; x += 256) {
            int n  = x >> 5;
            int d4 = x & 31;
            float4 kv = *(const float4*)(Kg + (size_t)(kbase + n) * HDd + d4 * 4);
            int col = (n + d4 * 4) & 63;
            Ks[(d4 * 4 + 0) * 64 + col] = kv.x;
            Ks[(d4 * 4 + 1) * 64 + col] = kv.y;
            Ks[(d4 * 4 + 2) * 64 + col] = kv.z;
            Ks[(d4 * 4 + 3) * 64 + col] = kv.w;
            float4 vv = *(const float4*)(Vg + (size_t)(kbase + n) * HDd + d4 * 4);
            *(float4*)(Vs + n * 128 + d4 * 4) = vv;
        }
        __syncthreads();

        float s[4][4];
#pragma unroll
        for (int i = 0; i < 4; i++)
#pragma unroll
            for (int j = 0; j < 4; j++) s[i][j] = 0.f;

        const int cA = ty * 4;
        const int cB = tx * 4;
#pragma unroll 8
        for (int d4 = 0; d4 < 32; d4++) {
            int sk   = d4 * 4;
            int colA = (cA + sk) & 63;
            int colB = (cB + sk) & 63;
#pragma unroll
            for (int u = 0; u < 4; u++) {
                int dd = sk + u;
                float4 a = *(const float4*)(Qs + dd * 64 + colA);
                float4 b = *(const float4*)(Ks + dd * 64 + colB);
                float av[4] = {a.x, a.y, a.z, a.w};
                float bv[4] = {b.x, b.y, b.z, b.w};
#pragma unroll
                for (int i = 0; i < 4; i++)
#pragma unroll
                    for (int j = 0; j < 4; j++)
                        s[i][j] += av[i] * bv[j];
            }
        }

        const bool diag = (jt == iq);
#pragma unroll
        for (int i = 0; i < 4; i++)
#pragma unroll
            for (int j = 0; j < 4; j++) {
                float val = s[i][j] * scale;
                if (diag && (tx * 4 + j > ty * 4 + i)) val = -1e30f;
                s[i][j] = val;
            }

#pragma unroll
        for (int i = 0; i < 4; i++) {
            float mx = fmaxf(fmaxf(s[i][0], s[i][1]), fmaxf(s[i][2], s[i][3]));
#pragma unroll
            for (int off = 1; off < 16; off <<= 1)
                mx = fmaxf(mx, __shfl_xor_sync(0xffffffffu, mx, off));
            float mnew  = fmaxf(mrow[i], mx);
            float alpha = __expf(mrow[i] - mnew);
            mrow[i] = mnew;

            float lsum = 0.f;
#pragma unroll
            for (int j = 0; j < 4; j++) {
                float p = __expf(s[i][j] - mnew);
                s[i][j] = p;
                lsum += p;
            }
#pragma unroll
            for (int off = 1; off < 16; off <<= 1)
                lsum += __shfl_xor_sync(0xffffffffu, lsum, off);
            lrow[i] = lrow[i] * alpha + lsum;

#pragma unroll
            for (int j = 0; j < 8; j++) acc[i][j] *= alpha;

#pragma unroll
            for (int j = 0; j < 4; j++)
                Ps[(tx * 4 + j) * 65 + ty * 4 + i] = s[i][j];
        }
        __syncthreads();

#pragma unroll 4
        for (int n = 0; n < 64; n++) {
            float p0 = Ps[n * 65 + ty * 4 + 0];
            float p1 = Ps[n * 65 + ty * 4 + 1];
            float p2 = Ps[n * 65 + ty * 4 + 2];
            float p3 = Ps[n * 65 + ty * 4 + 3];
            float4 v0 = *(const float4*)(Vs + n * 128 + tx * 4);
            float4 v1 = *(const float4*)(Vs + n * 128 + 64 + tx * 4);
            float vv0[4] = {v0.x, v0.y, v0.z, v0.w};
            float vv1[4] = {v1.x, v1.y, v1.z, v1.w};
            float pp[4] = {p0, p1, p2, p3};
#pragma unroll
            for (int i = 0; i < 4; i++)
#pragma unroll
                for (int j = 0; j < 4; j++) {
                    acc[i][j]     += pp[i] * vv0[j];
                    acc[i][4 + j] += pp[i] * vv1[j];
                }
        }
    }

    const int b  = bh >> 4;
    const int nh = bh & 15;
#pragma unroll
    for (int i = 0; i < 4; i++) {
        float inv = 1.f / lrow[i];
        int m = iq * 64 + ty * 4 + i;
        float* dst = g_attn + (size_t)(b * Sq + m) * Hh + nh * HDd;
        *(float4*)(dst + tx * 4) =
            make_float4(acc[i][0] * inv, acc[i][1] * inv, acc[i][2] * inv, acc[i][3] * inv);
        *(float4*)(dst + 64 + tx * 4) =
            make_float4(acc[i][4] * inv, acc[i][5] * inv, acc[i][6] * inv, acc[i][7] * inv);
    }
}

// ============================================================================
// launch
// ============================================================================
extern "C" void kernel_launch(void* const* d_in, const int* in_sizes, int n_in,
                              void* d_out, int out_size) {
    const float* hidden = (const float*)d_in[0];
    const float* cosT   = (const float*)d_in[1];
    const float* sinT   = (const float*)d_in[2];
    // d_in[3] = attention_mask (causal; analytic)
    const float* w_qkv  = (const float*)d_in[4];
    const float* w_o    = (const float*)d_in[5];
    float* out = (float*)d_out;

    float *p_qkv, *p_attn;
    cudaGetSymbolAddress((void**)&p_qkv, g_qkv);
    cudaGetSymbolAddress((void**)&p_attn, g_attn);

    __nv_bfloat16 *p_hhi, *p_hlo, *p_wqhi, *p_wqlo, *p_ahi, *p_alo, *p_wohi, *p_wolo;
    cudaGetSymbolAddress((void**)&p_hhi, g_hhi);
    cudaGetSymbolAddress((void**)&p_hlo, g_hlo);
    cudaGetSymbolAddress((void**)&p_wqhi, g_wqhi);
    cudaGetSymbolAddress((void**)&p_wqlo, g_wqlo);
    cudaGetSymbolAddress((void**)&p_ahi, g_ahi);
    cudaGetSymbolAddress((void**)&p_alo, g_alo);
    cudaGetSymbolAddress((void**)&p_wohi, g_wohi);
    cudaGetSymbolAddress((void**)&p_wolo, g_wolo);

    cudaFuncSetAttribute(fattn, cudaFuncAttributeMaxDynamicSharedMemorySize, FA_SMEM);

    // 0) bf16 hi/lo splits of hidden and weights
    {
        int n4 = (4096 * 2048) / 4;
        split_hilo<<<(n4 + 255) / 256, 256>>>(hidden, p_hhi, p_hlo, n4);
    }
    {
        int n4 = (6144 * 2048) / 4;
        split_hilo<<<(n4 + 255) / 256, 256>>>(w_qkv, p_wqhi, p_wqlo, n4);
    }
    {
        int n4 = (2048 * 2048) / 4;
        split_hilo<<<(n4 + 255) / 256, 256>>>(w_o, p_wohi, p_wolo, n4);
    }

    // 1) QKV = hidden @ w_qkv^T  (HMMA bf16x3)
    gemm_mma<<<dim3(QKV_N / 128, M_ROWS / 128), 256>>>(
        p_hhi, p_hlo, p_wqhi, p_wqlo, p_qkv, M_ROWS, QKV_N, Hh);

    // 2) RoPE + split into q/k/v
    rope_split<<<(Bsz * NHd * Sq * HDd) / 256, 256>>>(cosT, sinT);

    // 3) causal flash attention (fp32)
    fattn<<<dim3(Sq / 64, Bsz * NHd), 256, FA_SMEM>>>();

    // 4) split attn output, then out = attn @ w_o^T (HMMA bf16x3)
    {
        int n4 = (4096 * 2048) / 4;
        split_hilo<<<(n4 + 255) / 256, 256>>>(p_attn, p_ahi, p_alo, n4);
    }
    gemm_mma<<<dim3(Hh / 128, M_ROWS / 128), 256>>>(
        p_ahi, p_alo, p_wohi, p_wolo, out, M_ROWS, Hh, Hh);
}

// round 16
// speedup vs baseline: 2.4210x; 2.4210x over previous
#include <cuda_runtime.h>
#include <cuda_bf16.h>
#include <cstdint>

// Problem constants
#define Bsz 2
#define Sq  2048
#define Hh  2048
#define NHd 16
#define HDd 128

static const int M_ROWS = Bsz * Sq;    // 4096
static const int QKV_N  = 3 * Hh;      // 6144

// ---------------- scratch (device globals; no allocation allowed) -----------
__device__ float g_qkv[4096 * 6144];   // [b*S+s][3H] fp32 (QKV GEMM out)

// bf16 hi/lo split buffers (GEMM operands)
__device__ __nv_bfloat16 g_hhi[4096 * 2048], g_hlo[4096 * 2048];
__device__ __nv_bfloat16 g_wqhi[6144 * 2048], g_wqlo[6144 * 2048];
__device__ __nv_bfloat16 g_ahi[4096 * 2048], g_alo[4096 * 2048];   // attn out (O-proj A)
__device__ __nv_bfloat16 g_wohi[2048 * 2048], g_wolo[2048 * 2048];

// RoPE'd q/k/v, bf16 hi/lo, [bh][s][d]
#define QKV_ELEMS (Bsz * NHd * Sq * HDd)
__device__ __nv_bfloat16 g_qhi[QKV_ELEMS], g_qlo[QKV_ELEMS];
__device__ __nv_bfloat16 g_khi[QKV_ELEMS], g_klo[QKV_ELEMS];
__device__ __nv_bfloat16 g_vhi[QKV_ELEMS], g_vlo[QKV_ELEMS];

// ---------------- PTX helpers (compute_103-safe) -----------------------------
__device__ __forceinline__ uint32_t smem_u32(const void* p) {
    uint32_t a;
    asm("{ .reg .u64 t; cvta.to.shared.u64 t, %1; cvt.u32.u64 %0, t; }" : "=r"(a) : "l"(p));
    return a;
}
__device__ __forceinline__ void ldm_x4(uint32_t* r, uint32_t addr) {
    asm volatile("ldmatrix.sync.aligned.m8n8.x4.shared.b16 {%0,%1,%2,%3}, [%4];"
                 : "=r"(r[0]), "=r"(r[1]), "=r"(r[2]), "=r"(r[3]) : "r"(addr));
}
__device__ __forceinline__ void ldm_x2(uint32_t* r, uint32_t addr) {
    asm volatile("ldmatrix.sync.aligned.m8n8.x2.shared.b16 {%0,%1}, [%2];"
                 : "=r"(r[0]), "=r"(r[1]) : "r"(addr));
}
__device__ __forceinline__ void ldm_x2_t(uint32_t* r, uint32_t addr) {
    asm volatile("ldmatrix.sync.aligned.m8n8.x2.trans.shared.b16 {%0,%1}, [%2];"
                 : "=r"(r[0]), "=r"(r[1]) : "r"(addr));
}
__device__ __forceinline__ void mma16816(float* d, const uint32_t* a, const uint32_t* b) {
    asm volatile("mma.sync.aligned.m16n8k16.row.col.f32.bf16.bf16.f32 "
                 "{%0,%1,%2,%3}, {%4,%5,%6,%7}, {%8,%9}, {%0,%1,%2,%3};"
                 : "+f"(d[0]), "+f"(d[1]), "+f"(d[2]), "+f"(d[3])
                 : "r"(a[0]), "r"(a[1]), "r"(a[2]), "r"(a[3]), "r"(b[0]), "r"(b[1]));
}
#define CP16(dst, src) \
    asm volatile("cp.async.cg.shared.global [%0], [%1], 16;" \
                 :: "r"(dst), "l"(__cvta_generic_to_global(src)) : "memory")
#define CP_COMMIT() asm volatile("cp.async.commit_group;" ::: "memory")
#define CP_WAIT1()  asm volatile("cp.async.wait_group 1;" ::: "memory")
#define CP_WAIT0()  asm volatile("cp.async.wait_group 0;" ::: "memory")

// split a pair of floats into packed bf16x2 hi and lo residual
__device__ __forceinline__ void split2(float a, float b, uint32_t& hi, uint32_t& lo) {
    __nv_bfloat16 ah = __float2bfloat16(a), bh = __float2bfloat16(b);
    float ar = a - __bfloat162float(ah);
    float br = b - __bfloat162float(bh);
    __nv_bfloat162 hv = __halves2bfloat162(ah, bh);      // .x = low 16 bits
    __nv_bfloat162 lv = __floats2bfloat162_rn(ar, br);
    hi = *reinterpret_cast<uint32_t*>(&hv);
    lo = *reinterpret_cast<uint32_t*>(&lv);
}

// ============================================================================
// fp32 -> bf16 hi/lo split (vectorized x4)
// ============================================================================
__global__ __launch_bounds__(256)
void split_hilo(const float* __restrict__ x, __nv_bfloat16* __restrict__ hi,
                __nv_bfloat16* __restrict__ lo, int n4) {
    int i = blockIdx.x * 256 + threadIdx.x;
    if (i >= n4) return;
    float4 v = ((const float4*)x)[i];
    __nv_bfloat16 h0 = __float2bfloat16(v.x);
    __nv_bfloat16 h1 = __float2bfloat16(v.y);
    __nv_bfloat16 h2 = __float2bfloat16(v.z);
    __nv_bfloat16 h3 = __float2bfloat16(v.w);
    ushort4 H, L;
    H.x = __bfloat16_as_ushort(h0); H.y = __bfloat16_as_ushort(h1);
    H.z = __bfloat16_as_ushort(h2); H.w = __bfloat16_as_ushort(h3);
    L.x = __bfloat16_as_ushort(__float2bfloat16(v.x - __bfloat162float(h0)));
    L.y = __bfloat16_as_ushort(__float2bfloat16(v.y - __bfloat162float(h1)));
    L.z = __bfloat16_as_ushort(__float2bfloat16(v.z - __bfloat162float(h2)));
    L.w = __bfloat16_as_ushort(__float2bfloat16(v.w - __bfloat162float(h3)));
    ((ushort4*)hi)[i] = H;
    ((ushort4*)lo)[i] = L;
}

// ============================================================================
// HMMA bf16x3 GEMM (NT) with cp.async double buffering.
// CTA tile 128x128, BK=32. 8 warps 2(m)x4(n); warp tile 64x32.
// dyn smem: 2 stages x 4 tiles x [128][40] bf16 = 81920 B.
// ============================================================================
#define GP 40
#define GTILE_B (128 * GP * 2)          // 10240 bytes per tile
#define GSTAGE_B (4 * GTILE_B)          // 40960
#define GEMM_SMEM (2 * GSTAGE_B)        // 81920

__global__ __launch_bounds__(256, 2)
void gemm_mma(const __nv_bfloat16* __restrict__ Ahi, const __nv_bfloat16* __restrict__ Alo,
              const __nv_bfloat16* __restrict__ Bhi, const __nv_bfloat16* __restrict__ Blo,
              float* __restrict__ C, int M, int N, int K) {
    extern __shared__ __nv_bfloat16 gsm[];
    const uint32_t sb = smem_u32(gsm);

    const int tid  = threadIdx.x;
    const int wid  = tid >> 5;
    const int lane = tid & 31;
    const int warp_m = wid & 1;
    const int warp_n = wid >> 1;
    const int m0 = blockIdx.y * 128;
    const int n0 = blockIdx.x * 128;

    const __nv_bfloat16* a_hi = Ahi + (size_t)m0 * K;
    const __nv_bfloat16* a_lo = Alo + (size_t)m0 * K;
    const __nv_bfloat16* b_hi = Bhi + (size_t)n0 * K;
    const __nv_bfloat16* b_lo = Blo + (size_t)n0 * K;

    auto issue = [&](int c, int st) {
        const uint32_t s0 = sb + st * GSTAGE_B;
#pragma unroll
        for (int x = tid; x < 512; x += 256) {
            int r = x >> 2, seg = x & 3;
            size_t go = (size_t)r * K + c * 32 + seg * 8;
            uint32_t so = (uint32_t)(r * GP + seg * 8) * 2;
            CP16(s0 + so,               a_hi + go);
            CP16(s0 + GTILE_B + so,     a_lo + go);
            CP16(s0 + 2 * GTILE_B + so, b_hi + go);
            CP16(s0 + 3 * GTILE_B + so, b_lo + go);
        }
    };

    const uint32_t aoff = ((warp_m * 64 + (lane & 15)) * GP + (lane >> 4) * 8) * 2;
    const uint32_t boff = ((warp_n * 32 + (lane & 7)) * GP + ((lane >> 3) & 1) * 8) * 2;

    float acc[4][4][4];
#pragma unroll
    for (int i = 0; i < 4; i++)
#pragma unroll
        for (int j = 0; j < 4; j++)
#pragma unroll
            for (int q = 0; q < 4; q++) acc[i][j][q] = 0.f;

    const int nchunk = K >> 5;
    issue(0, 0);
    CP_COMMIT();

    for (int c = 0; c < nchunk; c++) {
        const int st = c & 1;
        if (c + 1 < nchunk) {
            issue(c + 1, st ^ 1);
            CP_COMMIT();
            CP_WAIT1();
        } else {
            CP_WAIT0();
        }
        __syncthreads();

        const uint32_t sAhi_b = sb + st * GSTAGE_B;
        const uint32_t sAlo_b = sAhi_b + GTILE_B;
        const uint32_t sBhi_b = sAhi_b + 2 * GTILE_B;
        const uint32_t sBlo_b = sAhi_b + 3 * GTILE_B;

#pragma unroll
        for (int ks = 0; ks < 2; ks++) {
            const uint32_t kso = ks * 32;
            uint32_t fahi[4][4], falo[4][4], fb[4][2];
#pragma unroll
            for (int mi = 0; mi < 4; mi++) {
                uint32_t ao = aoff + (uint32_t)(mi * 16 * GP) * 2 + kso;
                ldm_x4(fahi[mi], sAhi_b + ao);
                ldm_x4(falo[mi], sAlo_b + ao);
            }
#pragma unroll
            for (int ni = 0; ni < 4; ni++) {
                uint32_t bo = boff + (uint32_t)(ni * 8 * GP) * 2 + kso;
                ldm_x2(fb[ni], sBhi_b + bo);
            }
#pragma unroll
            for (int mi = 0; mi < 4; mi++)
#pragma unroll
                for (int ni = 0; ni < 4; ni++) {
                    mma16816(acc[mi][ni], fahi[mi], fb[ni]);
                    mma16816(acc[mi][ni], falo[mi], fb[ni]);
                }
#pragma unroll
            for (int ni = 0; ni < 4; ni++) {
                uint32_t bo = boff + (uint32_t)(ni * 8 * GP) * 2 + kso;
                ldm_x2(fb[ni], sBlo_b + bo);
            }
#pragma unroll
            for (int mi = 0; mi < 4; mi++)
#pragma unroll
                for (int ni = 0; ni < 4; ni++)
                    mma16816(acc[mi][ni], fahi[mi], fb[ni]);
        }
        __syncthreads();
    }

    const int er = lane >> 2;
    const int ec = (lane & 3) * 2;
#pragma unroll
    for (int mi = 0; mi < 4; mi++) {
#pragma unroll
        for (int ni = 0; ni < 4; ni++) {
            int row = m0 + warp_m * 64 + mi * 16 + er;
            int col = n0 + warp_n * 32 + ni * 8 + ec;
            float* p0 = C + (size_t)row * N + col;
            float* p1 = C + (size_t)(row + 8) * N + col;
            p0[0] = acc[mi][ni][0]; p0[1] = acc[mi][ni][1];
            p1[0] = acc[mi][ni][2]; p1[1] = acc[mi][ni][3];
        }
    }
}

// ============================================================================
// RoPE + layout split: g_qkv [b,s,3,nh,d] -> bf16 hi/lo q/k/v [bh][s][d]
// ============================================================================
__global__ __launch_bounds__(256)
void rope_split(const float* __restrict__ cosT, const float* __restrict__ sinT) {
    int idx = blockIdx.x * blockDim.x + threadIdx.x;
    int d  = idx & 127;
    int nh = (idx >> 7) & 15;
    int s  = (idx >> 11) & 2047;
    int b  = idx >> 22;

    size_t base = ((size_t)(b * Sq + s)) * (3 * Hh) + nh * HDd;
    int dp = (d < 64) ? d + 64 : d - 64;
    float c  = cosT[s * HDd + d];
    float sn = sinT[s * HDd + d];
    size_t o = (((size_t)(b * NHd + nh)) * Sq + s) * HDd + d;

    float x  = g_qkv[base + d];
    float xp = g_qkv[base + dp];
    float rot = (d < 64) ? -xp : xp;
    float qv = x * c + rot * sn;
    __nv_bfloat16 qh = __float2bfloat16(qv);
    g_qhi[o] = qh;
    g_qlo[o] = __float2bfloat16(qv - __bfloat162float(qh));

    x  = g_qkv[base + Hh + d];
    xp = g_qkv[base + Hh + dp];
    rot = (d < 64) ? -xp : xp;
    float kv = x * c + rot * sn;
    __nv_bfloat16 kh = __float2bfloat16(kv);
    g_khi[o] = kh;
    g_klo[o] = __float2bfloat16(kv - __bfloat162float(kh));

    float vv = g_qkv[base + 2 * Hh + d];
    __nv_bfloat16 vh = __float2bfloat16(vv);
    g_vhi[o] = vh;
    g_vlo[o] = __float2bfloat16(vv - __bfloat162float(vh));
}

// ============================================================================
// Tensor-core flash attention (bf16 hi/lo x3, fp32 softmax), causal.
// CTA: 128 Q rows, 8 warps x 16 rows. KV tiles of 64, cp.async double-buffered.
// smem: Qhi/Qlo [128][136] + 2 stages x (Khi,Klo,Vhi,Vlo)[64][136] bf16.
// ============================================================================
#define AP 136
#define Q_TILE_B (128 * AP * 2)        // 34816 bytes per Q array
#define KV_TILE_B (64 * AP * 2)        // 17408 bytes per KV array
#define KV_STAGE_B (4 * KV_TILE_B)     // 69632
#define FA_SMEM (2 * Q_TILE_B + 2 * KV_STAGE_B)   // 208896

__global__ __launch_bounds__(256, 1)
void fattn_mma() {
    extern __shared__ __nv_bfloat16 fsm[];
    const uint32_t sb = smem_u32(fsm);

    const int bh = blockIdx.y;
    const int iq = 15 - blockIdx.x;       // heavy Q blocks first
    const int tid  = threadIdx.x;
    const int wid  = tid >> 5;
    const int lane = tid & 31;
    const int b  = bh >> 4;
    const int nh = bh & 15;

    const __nv_bfloat16* qh = g_qhi + (size_t)bh * Sq * HDd;
    const __nv_bfloat16* ql = g_qlo + (size_t)bh * Sq * HDd;
    const __nv_bfloat16* kh = g_khi + (size_t)bh * Sq * HDd;
    const __nv_bfloat16* kl = g_klo + (size_t)bh * Sq * HDd;
    const __nv_bfloat16* vh = g_vhi + (size_t)bh * Sq * HDd;
    const __nv_bfloat16* vl = g_vlo + (size_t)bh * Sq * HDd;

    const uint32_t sQhi = sb;
    const uint32_t sQlo = sb + Q_TILE_B;
    const uint32_t kvbase = sb + 2 * Q_TILE_B;

    // prologue: Q tile (hi+lo) + KV tile 0 in one cp.async group
    for (int x = tid; x < 2048; x += 256) {   // 128 rows x 16 segs
        int r = x >> 4, seg = x & 15;
        size_t go = (size_t)(iq * 128 + r) * HDd + seg * 8;
        uint32_t so = (uint32_t)(r * AP + seg * 8) * 2;
        CP16(sQhi + so, qh + go);
        CP16(sQlo + so, ql + go);
    }
    auto issue_kv = [&](int jt, int st) {
        const uint32_t s0 = kvbase + st * KV_STAGE_B;
#pragma unroll
        for (int x = tid; x < 1024; x += 256) {   // 64 rows x 16 segs
            int r = x >> 4, seg = x & 15;
            size_t go = (size_t)(jt * 64 + r) * HDd + seg * 8;
            uint32_t so = (uint32_t)(r * AP + seg * 8) * 2;
            CP16(s0 + so,                kh + go);
            CP16(s0 + KV_TILE_B + so,    kl + go);
            CP16(s0 + 2 * KV_TILE_B + so, vh + go);
            CP16(s0 + 3 * KV_TILE_B + so, vl + go);
        }
    };
    issue_kv(0, 0);
    CP_COMMIT();

    float o[16][4];
#pragma unroll
    for (int n2 = 0; n2 < 16; n2++)
#pragma unroll
        for (int e = 0; e < 4; e++) o[n2][e] = 0.f;
    float m0r = -1e30f, m1r = -1e30f, l0 = 0.f, l1 = 0.f;

    const int ntiles = 2 * iq + 2;
    const float scale = 0.08838834764831845f;   // 1/sqrt(128)

    const uint32_t q_aoff = ((wid * 16 + (lane & 15)) * AP + (lane >> 4) * 8) * 2;
    const uint32_t k_boff = (((lane & 7)) * AP + ((lane >> 3) & 1) * 8) * 2;
    const uint32_t v_off  = ((lane & 15) * AP) * 2;
    const int r0 = iq * 128 + wid * 16 + (lane >> 2);

    for (int jt = 0; jt < ntiles; jt++) {
        const int st = jt & 1;
        if (jt + 1 < ntiles) {
            issue_kv(jt + 1, st ^ 1);
            CP_COMMIT();
            CP_WAIT1();
        } else {
            CP_WAIT0();
        }
        __syncthreads();

        const uint32_t sK_hi = kvbase + st * KV_STAGE_B;
        const uint32_t sK_lo = sK_hi + KV_TILE_B;
        const uint32_t sV_hi = sK_hi + 2 * KV_TILE_B;
        const uint32_t sV_lo = sK_hi + 3 * KV_TILE_B;

        // ---- S = Q K^T (hi/lo x3) ----
        float s[8][4];
#pragma unroll
        for (int n = 0; n < 8; n++)
#pragma unroll
            for (int e = 0; e < 4; e++) s[n][e] = 0.f;

#pragma unroll
        for (int ks = 0; ks < 8; ks++) {
            uint32_t qhf[4], qlf[4], kb[2];
            uint32_t ao = q_aoff + ks * 32;
            ldm_x4(qhf, sQhi + ao);
            ldm_x4(qlf, sQlo + ao);
#pragma unroll
            for (int n = 0; n < 8; n++) {
                uint32_t bo = k_boff + (uint32_t)(n * 8 * AP) * 2 + ks * 32;
                ldm_x2(kb, sK_hi + bo);
                mma16816(s[n], qhf, kb);
                mma16816(s[n], qlf, kb);
                ldm_x2(kb, sK_lo + bo);
                mma16816(s[n], qhf, kb);
            }
        }

        // ---- scale + causal mask (only tiles touching the diagonal) ----
        const bool mtile = (jt >= ntiles - 2);
#pragma unroll
        for (int n = 0; n < 8; n++) {
#pragma unroll
            for (int e = 0; e < 4; e++) {
                float v = s[n][e] * scale;
                if (mtile) {
                    int row = r0 + ((e >= 2) ? 8 : 0);
                    int col = jt * 64 + n * 8 + (lane & 3) * 2 + (e & 1);
                    if (col > row) v = -1e30f;
                }
                s[n][e] = v;
            }
        }

        // ---- online softmax (rows r0 and r0+8) ----
        float mx0 = -1e30f, mx1 = -1e30f;
#pragma unroll
        for (int n = 0; n < 8; n++) {
            mx0 = fmaxf(mx0, fmaxf(s[n][0], s[n][1]));
            mx1 = fmaxf(mx1, fmaxf(s[n][2], s[n][3]));
        }
        mx0 = fmaxf(mx0, __shfl_xor_sync(0xffffffffu, mx0, 1));
        mx0 = fmaxf(mx0, __shfl_xor_sync(0xffffffffu, mx0, 2));
        mx1 = fmaxf(mx1, __shfl_xor_sync(0xffffffffu, mx1, 1));
        mx1 = fmaxf(mx1, __shfl_xor_sync(0xffffffffu, mx1, 2));
        float mn0 = fmaxf(m0r, mx0), mn1 = fmaxf(m1r, mx1);
        float al0 = __expf(m0r - mn0), al1 = __expf(m1r - mn1);
        m0r = mn0; m1r = mn1;

        float ls0 = 0.f, ls1 = 0.f;
#pragma unroll
        for (int n = 0; n < 8; n++) {
            s[n][0] = __expf(s[n][0] - mn0); ls0 += s[n][0];
            s[n][1] = __expf(s[n][1] - mn0); ls0 += s[n][1];
            s[n][2] = __expf(s[n][2] - mn1); ls1 += s[n][2];
            s[n][3] = __expf(s[n][3] - mn1); ls1 += s[n][3];
        }
        ls0 += __shfl_xor_sync(0xffffffffu, ls0, 1);
        ls0 += __shfl_xor_sync(0xffffffffu, ls0, 2);
        ls1 += __shfl_xor_sync(0xffffffffu, ls1, 1);
        ls1 += __shfl_xor_sync(0xffffffffu, ls1, 2);
        l0 = l0 * al0 + ls0;
        l1 = l1 * al1 + ls1;

#pragma unroll
        for (int n2 = 0; n2 < 16; n2++) {
            o[n2][0] *= al0; o[n2][1] *= al0;
            o[n2][2] *= al1; o[n2][3] *= al1;
        }

        // ---- O += P V (P hi/lo from registers, V hi/lo x3) ----
#pragma unroll
        for (int kp = 0; kp < 4; kp++) {
            uint32_t pa_hi[4], pa_lo[4];
            split2(s[2 * kp][0],     s[2 * kp][1],     pa_hi[0], pa_lo[0]);
            split2(s[2 * kp][2],     s[2 * kp][3],     pa_hi[1], pa_lo[1]);
            split2(s[2 * kp + 1][0], s[2 * kp + 1][1], pa_hi[2], pa_lo[2]);
            split2(s[2 * kp + 1][2], s[2 * kp + 1][3], pa_hi[3], pa_lo[3]);
#pragma unroll
            for (int n2 = 0; n2 < 16; n2++) {
                uint32_t vb[2];
                uint32_t vo = v_off + (uint32_t)(kp * 16 * AP) * 2 + n2 * 16;
                ldm_x2_t(vb, sV_hi + vo);
                mma16816(o[n2], pa_hi, vb);
                mma16816(o[n2], pa_lo, vb);
                ldm_x2_t(vb, sV_lo + vo);
                mma16816(o[n2], pa_hi, vb);
            }
        }
        __syncthreads();   // stage st free for reuse
    }

    // ---- epilogue: normalize, split hi/lo, write O-proj A operand ----
    const float inv0 = 1.f / l0, inv1 = 1.f / l1;
    const int col0 = (lane & 3) * 2;
    const size_t base0 = (size_t)(b * Sq + r0) * Hh + nh * HDd;
    const size_t base1 = base0 + (size_t)8 * Hh;
#pragma unroll
    for (int n2 = 0; n2 < 16; n2++) {
        uint32_t hv, lv;
        split2(o[n2][0] * inv0, o[n2][1] * inv0, hv, lv);
        *(uint32_t*)(&g_ahi[base0 + n2 * 8 + col0]) = hv;
        *(uint32_t*)(&g_alo[base0 + n2 * 8 + col0]) = lv;
        split2(o[n2][2] * inv1, o[n2][3] * inv1, hv, lv);
        *(uint32_t*)(&g_ahi[base1 + n2 * 8 + col0]) = hv;
        *(uint32_t*)(&g_alo[base1 + n2 * 8 + col0]) = lv;
    }
}

// ============================================================================
// launch
// ============================================================================
extern "C" void kernel_launch(void* const* d_in, const int* in_sizes, int n_in,
                              void* d_out, int out_size) {
    const float* hidden = (const float*)d_in[0];
    const float* cosT   = (const float*)d_in[1];
    const float* sinT   = (const float*)d_in[2];
    // d_in[3] = attention_mask (causal; analytic)
    const float* w_qkv  = (const float*)d_in[4];
    const float* w_o    = (const float*)d_in[5];
    float* out = (float*)d_out;

    float* p_qkv;
    cudaGetSymbolAddress((void**)&p_qkv, g_qkv);

    __nv_bfloat16 *p_hhi, *p_hlo, *p_wqhi, *p_wqlo, *p_ahi, *p_alo, *p_wohi, *p_wolo;
    cudaGetSymbolAddress((void**)&p_hhi, g_hhi);
    cudaGetSymbolAddress((void**)&p_hlo, g_hlo);
    cudaGetSymbolAddress((void**)&p_wqhi, g_wqhi);
    cudaGetSymbolAddress((void**)&p_wqlo, g_wqlo);
    cudaGetSymbolAddress((void**)&p_ahi, g_ahi);
    cudaGetSymbolAddress((void**)&p_alo, g_alo);
    cudaGetSymbolAddress((void**)&p_wohi, g_wohi);
    cudaGetSymbolAddress((void**)&p_wolo, g_wolo);

    cudaFuncSetAttribute(gemm_mma, cudaFuncAttributeMaxDynamicSharedMemorySize, GEMM_SMEM);
    cudaFuncSetAttribute(fattn_mma, cudaFuncAttributeMaxDynamicSharedMemorySize, FA_SMEM);

    // 0) bf16 hi/lo splits
    split_hilo<<<(4096 * 2048 / 4 + 255) / 256, 256>>>(hidden, p_hhi, p_hlo, 4096 * 2048 / 4);
    split_hilo<<<(6144 * 2048 / 4 + 255) / 256, 256>>>(w_qkv, p_wqhi, p_wqlo, 6144 * 2048 / 4);
    split_hilo<<<(2048 * 2048 / 4 + 255) / 256, 256>>>(w_o, p_wohi, p_wolo, 2048 * 2048 / 4);

    // 1) QKV = hidden @ w_qkv^T
    gemm_mma<<<dim3(QKV_N / 128, M_ROWS / 128), 256, GEMM_SMEM>>>(
        p_hhi, p_hlo, p_wqhi, p_wqlo, p_qkv, M_ROWS, QKV_N, Hh);

    // 2) RoPE + split into bf16 hi/lo q/k/v
    rope_split<<<QKV_ELEMS / 256, 256>>>(cosT, sinT);

    // 3) tensor-core causal flash attention (writes g_ahi/g_alo directly)
    fattn_mma<<<dim3(Sq / 128, Bsz * NHd), 256, FA_SMEM>>>();

    // 4) out = attn @ w_o^T
    gemm_mma<<<dim3(Hh / 128, M_ROWS / 128), 256, GEMM_SMEM>>>(
        p_ahi, p_alo, p_wohi, p_wolo, out, M_ROWS, Hh, Hh);
}

// round 17
// speedup vs baseline: 2.4263x; 1.0022x over previous
#include <cuda_runtime.h>
#include <cuda_bf16.h>
#include <cstdint>

// Problem constants
#define Bsz 2
#define Sq  2048
#define Hh  2048
#define NHd 16
#define HDd 128

static const int M_ROWS = Bsz * Sq;    // 4096
static const int QKV_N  = 3 * Hh;      // 6144

// ---------------- scratch (device globals; no allocation allowed) -----------
__device__ float g_qkv[4096 * 6144];   // [b*S+s][3H] fp32 (QKV GEMM out)

// bf16 hi/lo split buffers (GEMM operands)
__device__ __nv_bfloat16 g_hhi[4096 * 2048], g_hlo[4096 * 2048];
__device__ __nv_bfloat16 g_wqhi[6144 * 2048], g_wqlo[6144 * 2048];
__device__ __nv_bfloat16 g_ahi[4096 * 2048], g_alo[4096 * 2048];   // attn out (O-proj A)
__device__ __nv_bfloat16 g_wohi[2048 * 2048], g_wolo[2048 * 2048];

// RoPE'd q/k/v, bf16 hi/lo, [bh][s][d]
#define QKV_ELEMS (Bsz * NHd * Sq * HDd)
__device__ __nv_bfloat16 g_qhi[QKV_ELEMS], g_qlo[QKV_ELEMS];
__device__ __nv_bfloat16 g_khi[QKV_ELEMS], g_klo[QKV_ELEMS];
__device__ __nv_bfloat16 g_vhi[QKV_ELEMS], g_vlo[QKV_ELEMS];

// ---------------- PTX helpers (compute_103-safe) -----------------------------
__device__ __forceinline__ uint32_t smem_u32(const void* p) {
    uint32_t a;
    asm("{ .reg .u64 t; cvta.to.shared.u64 t, %1; cvt.u32.u64 %0, t; }" : "=r"(a) : "l"(p));
    return a;
}
__device__ __forceinline__ void ldm_x4(uint32_t* r, uint32_t addr) {
    asm volatile("ldmatrix.sync.aligned.m8n8.x4.shared.b16 {%0,%1,%2,%3}, [%4];"
                 : "=r"(r[0]), "=r"(r[1]), "=r"(r[2]), "=r"(r[3]) : "r"(addr));
}
__device__ __forceinline__ void ldm_x2(uint32_t* r, uint32_t addr) {
    asm volatile("ldmatrix.sync.aligned.m8n8.x2.shared.b16 {%0,%1}, [%2];"
                 : "=r"(r[0]), "=r"(r[1]) : "r"(addr));
}
__device__ __forceinline__ void ldm_x2_t(uint32_t* r, uint32_t addr) {
    asm volatile("ldmatrix.sync.aligned.m8n8.x2.trans.shared.b16 {%0,%1}, [%2];"
                 : "=r"(r[0]), "=r"(r[1]) : "r"(addr));
}
__device__ __forceinline__ void mma16816(float* d, const uint32_t* a, const uint32_t* b) {
    asm volatile("mma.sync.aligned.m16n8k16.row.col.f32.bf16.bf16.f32 "
                 "{%0,%1,%2,%3}, {%4,%5,%6,%7}, {%8,%9}, {%0,%1,%2,%3};"
                 : "+f"(d[0]), "+f"(d[1]), "+f"(d[2]), "+f"(d[3])
                 : "r"(a[0]), "r"(a[1]), "r"(a[2]), "r"(a[3]), "r"(b[0]), "r"(b[1]));
}
#define CP16(dst, src) \
    asm volatile("cp.async.cg.shared.global [%0], [%1], 16;" \
                 :: "r"(dst), "l"(__cvta_generic_to_global(src)) : "memory")
#define CP_COMMIT() asm volatile("cp.async.commit_group;" ::: "memory")
#define CP_WAIT1()  asm volatile("cp.async.wait_group 1;" ::: "memory")
#define CP_WAIT0()  asm volatile("cp.async.wait_group 0;" ::: "memory")

// split a pair of floats into packed bf16x2 hi and lo residual
__device__ __forceinline__ void split2(float a, float b, uint32_t& hi, uint32_t& lo) {
    __nv_bfloat16 ah = __float2bfloat16(a), bh = __float2bfloat16(b);
    float ar = a - __bfloat162float(ah);
    float br = b - __bfloat162float(bh);
    __nv_bfloat162 hv = __halves2bfloat162(ah, bh);      // .x = low 16 bits
    __nv_bfloat162 lv = __floats2bfloat162_rn(ar, br);
    hi = *reinterpret_cast<uint32_t*>(&hv);
    lo = *reinterpret_cast<uint32_t*>(&lv);
}

// ============================================================================
// fp32 -> bf16 hi/lo split (vectorized x4)
// ============================================================================
__global__ __launch_bounds__(256)
void split_hilo(const float* __restrict__ x, __nv_bfloat16* __restrict__ hi,
                __nv_bfloat16* __restrict__ lo, int n4) {
    int i = blockIdx.x * 256 + threadIdx.x;
    if (i >= n4) return;
    float4 v = ((const float4*)x)[i];
    __nv_bfloat16 h0 = __float2bfloat16(v.x);
    __nv_bfloat16 h1 = __float2bfloat16(v.y);
    __nv_bfloat16 h2 = __float2bfloat16(v.z);
    __nv_bfloat16 h3 = __float2bfloat16(v.w);
    ushort4 H, L;
    H.x = __bfloat16_as_ushort(h0); H.y = __bfloat16_as_ushort(h1);
    H.z = __bfloat16_as_ushort(h2); H.w = __bfloat16_as_ushort(h3);
    L.x = __bfloat16_as_ushort(__float2bfloat16(v.x - __bfloat162float(h0)));
    L.y = __bfloat16_as_ushort(__float2bfloat16(v.y - __bfloat162float(h1)));
    L.z = __bfloat16_as_ushort(__float2bfloat16(v.z - __bfloat162float(h2)));
    L.w = __bfloat16_as_ushort(__float2bfloat16(v.w - __bfloat162float(h3)));
    ((ushort4*)hi)[i] = H;
    ((ushort4*)lo)[i] = L;
}

// ============================================================================
// HMMA bf16x3 GEMM (NT) with cp.async double buffering.
// CTA tile 128x128, BK=32. 8 warps 2(m)x4(n); warp tile 64x32.
// dyn smem: 2 stages x 4 tiles x [128][40] bf16 = 81920 B.
// ============================================================================
#define GP 40
#define GTILE_B (128 * GP * 2)          // 10240 bytes per tile
#define GSTAGE_B (4 * GTILE_B)          // 40960
#define GEMM_SMEM (2 * GSTAGE_B)        // 81920

__global__ __launch_bounds__(256, 2)
void gemm_mma(const __nv_bfloat16* __restrict__ Ahi, const __nv_bfloat16* __restrict__ Alo,
              const __nv_bfloat16* __restrict__ Bhi, const __nv_bfloat16* __restrict__ Blo,
              float* __restrict__ C, int M, int N, int K) {
    extern __shared__ __nv_bfloat16 gsm[];
    const uint32_t sb = smem_u32(gsm);

    const int tid  = threadIdx.x;
    const int wid  = tid >> 5;
    const int lane = tid & 31;
    const int warp_m = wid & 1;
    const int warp_n = wid >> 1;
    const int m0 = blockIdx.y * 128;
    const int n0 = blockIdx.x * 128;

    const __nv_bfloat16* a_hi = Ahi + (size_t)m0 * K;
    const __nv_bfloat16* a_lo = Alo + (size_t)m0 * K;
    const __nv_bfloat16* b_hi = Bhi + (size_t)n0 * K;
    const __nv_bfloat16* b_lo = Blo + (size_t)n0 * K;

    auto issue = [&](int c, int st) {
        const uint32_t s0 = sb + st * GSTAGE_B;
#pragma unroll
        for (int x = tid; x < 512; x += 256) {
            int r = x >> 2, seg = x & 3;
            size_t go = (size_t)r * K + c * 32 + seg * 8;
            uint32_t so = (uint32_t)(r * GP + seg * 8) * 2;
            CP16(s0 + so,               a_hi + go);
            CP16(s0 + GTILE_B + so,     a_lo + go);
            CP16(s0 + 2 * GTILE_B + so, b_hi + go);
            CP16(s0 + 3 * GTILE_B + so, b_lo + go);
        }
    };

    const uint32_t aoff = ((warp_m * 64 + (lane & 15)) * GP + (lane >> 4) * 8) * 2;
    const uint32_t boff = ((warp_n * 32 + (lane & 7)) * GP + ((lane >> 3) & 1) * 8) * 2;

    float acc[4][4][4];
#pragma unroll
    for (int i = 0; i < 4; i++)
#pragma unroll
        for (int j = 0; j < 4; j++)
#pragma unroll
            for (int q = 0; q < 4; q++) acc[i][j][q] = 0.f;

    const int nchunk = K >> 5;
    issue(0, 0);
    CP_COMMIT();

    for (int c = 0; c < nchunk; c++) {
        const int st = c & 1;
        if (c + 1 < nchunk) {
            issue(c + 1, st ^ 1);
            CP_COMMIT();
            CP_WAIT1();
        } else {
            CP_WAIT0();
        }
        __syncthreads();

        const uint32_t sAhi_b = sb + st * GSTAGE_B;
        const uint32_t sAlo_b = sAhi_b + GTILE_B;
        const uint32_t sBhi_b = sAhi_b + 2 * GTILE_B;
        const uint32_t sBlo_b = sAhi_b + 3 * GTILE_B;

#pragma unroll
        for (int ks = 0; ks < 2; ks++) {
            const uint32_t kso = ks * 32;
            uint32_t fahi[4][4], falo[4][4], fb[4][2];
#pragma unroll
            for (int mi = 0; mi < 4; mi++) {
                uint32_t ao = aoff + (uint32_t)(mi * 16 * GP) * 2 + kso;
                ldm_x4(fahi[mi], sAhi_b + ao);
                ldm_x4(falo[mi], sAlo_b + ao);
            }
#pragma unroll
            for (int ni = 0; ni < 4; ni++) {
                uint32_t bo = boff + (uint32_t)(ni * 8 * GP) * 2 + kso;
                ldm_x2(fb[ni], sBhi_b + bo);
            }
#pragma unroll
            for (int mi = 0; mi < 4; mi++)
#pragma unroll
                for (int ni = 0; ni < 4; ni++) {
                    mma16816(acc[mi][ni], fahi[mi], fb[ni]);
                    mma16816(acc[mi][ni], falo[mi], fb[ni]);
                }
#pragma unroll
            for (int ni = 0; ni < 4; ni++) {
                uint32_t bo = boff + (uint32_t)(ni * 8 * GP) * 2 + kso;
                ldm_x2(fb[ni], sBlo_b + bo);
            }
#pragma unroll
            for (int mi = 0; mi < 4; mi++)
#pragma unroll
                for (int ni = 0; ni < 4; ni++)
                    mma16816(acc[mi][ni], fahi[mi], fb[ni]);
        }
        __syncthreads();
    }

    const int er = lane >> 2;
    const int ec = (lane & 3) * 2;
#pragma unroll
    for (int mi = 0; mi < 4; mi++) {
#pragma unroll
        for (int ni = 0; ni < 4; ni++) {
            int row = m0 + warp_m * 64 + mi * 16 + er;
            int col = n0 + warp_n * 32 + ni * 8 + ec;
            float* p0 = C + (size_t)row * N + col;
            float* p1 = C + (size_t)(row + 8) * N + col;
            p0[0] = acc[mi][ni][0]; p0[1] = acc[mi][ni][1];
            p1[0] = acc[mi][ni][2]; p1[1] = acc[mi][ni][3];
        }
    }
}

// ============================================================================
// RoPE + layout split: g_qkv [b,s,3,nh,d] -> bf16 hi/lo q/k/v [bh][s][d]
// ============================================================================
__global__ __launch_bounds__(256)
void rope_split(const float* __restrict__ cosT, const float* __restrict__ sinT) {
    int idx = blockIdx.x * blockDim.x + threadIdx.x;
    int d  = idx & 127;
    int nh = (idx >> 7) & 15;
    int s  = (idx >> 11) & 2047;
    int b  = idx >> 22;

    size_t base = ((size_t)(b * Sq + s)) * (3 * Hh) + nh * HDd;
    int dp = (d < 64) ? d + 64 : d - 64;
    float c  = cosT[s * HDd + d];
    float sn = sinT[s * HDd + d];
    size_t o = (((size_t)(b * NHd + nh)) * Sq + s) * HDd + d;

    float x  = g_qkv[base + d];
    float xp = g_qkv[base + dp];
    float rot = (d < 64) ? -xp : xp;
    float qv = x * c + rot * sn;
    __nv_bfloat16 qh = __float2bfloat16(qv);
    g_qhi[o] = qh;
    g_qlo[o] = __float2bfloat16(qv - __bfloat162float(qh));

    x  = g_qkv[base + Hh + d];
    xp = g_qkv[base + Hh + dp];
    rot = (d < 64) ? -xp : xp;
    float kv = x * c + rot * sn;
    __nv_bfloat16 kh = __float2bfloat16(kv);
    g_khi[o] = kh;
    g_klo[o] = __float2bfloat16(kv - __bfloat162float(kh));

    float vv = g_qkv[base + 2 * Hh + d];
    __nv_bfloat16 vh = __float2bfloat16(vv);
    g_vhi[o] = vh;
    g_vlo[o] = __float2bfloat16(vv - __bfloat162float(vh));
}

// ============================================================================
// Tensor-core flash attention (bf16 hi/lo x3, fp32 softmax), causal.
// CTA: 128 Q rows, 8 warps x 16 rows. KV tiles of 64, cp.async double-buffered.
// smem: Qhi/Qlo [128][136] + 2 stages x (Khi,Klo,Vhi,Vlo)[64][136] bf16.
// ============================================================================
#define AP 136
#define Q_TILE_B (128 * AP * 2)        // 34816 bytes per Q array
#define KV_TILE_B (64 * AP * 2)        // 17408 bytes per KV array
#define KV_STAGE_B (4 * KV_TILE_B)     // 69632
#define FA_SMEM (2 * Q_TILE_B + 2 * KV_STAGE_B)   // 208896

__global__ __launch_bounds__(256, 1)
void fattn_mma() {
    extern __shared__ __nv_bfloat16 fsm[];
    const uint32_t sb = smem_u32(fsm);

    const int bh = blockIdx.y;
    const int iq = 15 - blockIdx.x;       // heavy Q blocks first
    const int tid  = threadIdx.x;
    const int wid  = tid >> 5;
    const int lane = tid & 31;
    const int b  = bh >> 4;
    const int nh = bh & 15;

    const __nv_bfloat16* qh = g_qhi + (size_t)bh * Sq * HDd;
    const __nv_bfloat16* ql = g_qlo + (size_t)bh * Sq * HDd;
    const __nv_bfloat16* kh = g_khi + (size_t)bh * Sq * HDd;
    const __nv_bfloat16* kl = g_klo + (size_t)bh * Sq * HDd;
    const __nv_bfloat16* vh = g_vhi + (size_t)bh * Sq * HDd;
    const __nv_bfloat16* vl = g_vlo + (size_t)bh * Sq * HDd;

    const uint32_t sQhi = sb;
    const uint32_t sQlo = sb + Q_TILE_B;
    const uint32_t kvbase = sb + 2 * Q_TILE_B;

    // prologue: Q tile (hi+lo) + KV tile 0 in one cp.async group
    for (int x = tid; x < 2048; x += 256) {   // 128 rows x 16 segs
        int r = x >> 4, seg = x & 15;
        size_t go = (size_t)(iq * 128 + r) * HDd + seg * 8;
        uint32_t so = (uint32_t)(r * AP + seg * 8) * 2;
        CP16(sQhi + so, qh + go);
        CP16(sQlo + so, ql + go);
    }
    auto issue_kv = [&](int jt, int st) {
        const uint32_t s0 = kvbase + st * KV_STAGE_B;
#pragma unroll
        for (int x = tid; x < 1024; x += 256) {   // 64 rows x 16 segs
            int r = x >> 4, seg = x & 15;
            size_t go = (size_t)(jt * 64 + r) * HDd + seg * 8;
            uint32_t so = (uint32_t)(r * AP + seg * 8) * 2;
            CP16(s0 + so,                kh + go);
            CP16(s0 + KV_TILE_B + so,    kl + go);
            CP16(s0 + 2 * KV_TILE_B + so, vh + go);
            CP16(s0 + 3 * KV_TILE_B + so, vl + go);
        }
    };
    issue_kv(0, 0);
    CP_COMMIT();

    float o[16][4];
#pragma unroll
    for (int n2 = 0; n2 < 16; n2++)
#pragma unroll
        for (int e = 0; e < 4; e++) o[n2][e] = 0.f;
    float m0r = -1e30f, m1r = -1e30f, l0 = 0.f, l1 = 0.f;

    const int ntiles = 2 * iq + 2;
    const float scale = 0.08838834764831845f;   // 1/sqrt(128)

    const uint32_t q_aoff = ((wid * 16 + (lane & 15)) * AP + (lane >> 4) * 8) * 2;
    const uint32_t k_boff = (((lane & 7)) * AP + ((lane >> 3) & 1) * 8) * 2;
    const uint32_t v_off  = ((lane & 15) * AP) * 2;
    const int r0 = iq * 128 + wid * 16 + (lane >> 2);

    for (int jt = 0; jt < ntiles; jt++) {
        const int st = jt & 1;
        if (jt + 1 < ntiles) {
            issue_kv(jt + 1, st ^ 1);
            CP_COMMIT();
            CP_WAIT1();
        } else {
            CP_WAIT0();
        }
        __syncthreads();

        const uint32_t sK_hi = kvbase + st * KV_STAGE_B;
        const uint32_t sK_lo = sK_hi + KV_TILE_B;
        const uint32_t sV_hi = sK_hi + 2 * KV_TILE_B;
        const uint32_t sV_lo = sK_hi + 3 * KV_TILE_B;

        // ---- S = Q K^T (hi/lo x3) ----
        float s[8][4];
#pragma unroll
        for (int n = 0; n < 8; n++)
#pragma unroll
            for (int e = 0; e < 4; e++) s[n][e] = 0.f;

#pragma unroll
        for (int ks = 0; ks < 8; ks++) {
            uint32_t qhf[4], qlf[4], kb[2];
            uint32_t ao = q_aoff + ks * 32;
            ldm_x4(qhf, sQhi + ao);
            ldm_x4(qlf, sQlo + ao);
#pragma unroll
            for (int n = 0; n < 8; n++) {
                uint32_t bo = k_boff + (uint32_t)(n * 8 * AP) * 2 + ks * 32;
                ldm_x2(kb, sK_hi + bo);
                mma16816(s[n], qhf, kb);
                mma16816(s[n], qlf, kb);
                ldm_x2(kb, sK_lo + bo);
                mma16816(s[n], qhf, kb);
            }
        }

        // ---- scale + causal mask (only tiles touching the diagonal) ----
        const bool mtile = (jt >= ntiles - 2);
#pragma unroll
        for (int n = 0; n < 8; n++) {
#pragma unroll
            for (int e = 0; e < 4; e++) {
                float v = s[n][e] * scale;
                if (mtile) {
                    int row = r0 + ((e >= 2) ? 8 : 0);
                    int col = jt * 64 + n * 8 + (lane & 3) * 2 + (e & 1);
                    if (col > row) v = -1e30f;
                }
                s[n][e] = v;
            }
        }

        // ---- online softmax (rows r0 and r0+8) ----
        float mx0 = -1e30f, mx1 = -1e30f;
#pragma unroll
        for (int n = 0; n < 8; n++) {
            mx0 = fmaxf(mx0, fmaxf(s[n][0], s[n][1]));
            mx1 = fmaxf(mx1, fmaxf(s[n][2], s[n][3]));
        }
        mx0 = fmaxf(mx0, __shfl_xor_sync(0xffffffffu, mx0, 1));
        mx0 = fmaxf(mx0, __shfl_xor_sync(0xffffffffu, mx0, 2));
        mx1 = fmaxf(mx1, __shfl_xor_sync(0xffffffffu, mx1, 1));
        mx1 = fmaxf(mx1, __shfl_xor_sync(0xffffffffu, mx1, 2));
        float mn0 = fmaxf(m0r, mx0), mn1 = fmaxf(m1r, mx1);
        float al0 = __expf(m0r - mn0), al1 = __expf(m1r - mn1);
        m0r = mn0; m1r = mn1;

        float ls0 = 0.f, ls1 = 0.f;
#pragma unroll
        for (int n = 0; n < 8; n++) {
            s[n][0] = __expf(s[n][0] - mn0); ls0 += s[n][0];
            s[n][1] = __expf(s[n][1] - mn0); ls0 += s[n][1];
            s[n][2] = __expf(s[n][2] - mn1); ls1 += s[n][2];
            s[n][3] = __expf(s[n][3] - mn1); ls1 += s[n][3];
        }
        ls0 += __shfl_xor_sync(0xffffffffu, ls0, 1);
        ls0 += __shfl_xor_sync(0xffffffffu, ls0, 2);
        ls1 += __shfl_xor_sync(0xffffffffu, ls1, 1);
        ls1 += __shfl_xor_sync(0xffffffffu, ls1, 2);
        l0 = l0 * al0 + ls0;
        l1 = l1 * al1 + ls1;

#pragma unroll
        for (int n2 = 0; n2 < 16; n2++) {
            o[n2][0] *= al0; o[n2][1] *= al0;
            o[n2][2] *= al1; o[n2][3] *= al1;
        }

        // ---- O += P V (P hi/lo from registers, V hi/lo x3) ----
#pragma unroll
        for (int kp = 0; kp < 4; kp++) {
            uint32_t pa_hi[4], pa_lo[4];
            split2(s[2 * kp][0],     s[2 * kp][1],     pa_hi[0], pa_lo[0]);
            split2(s[2 * kp][2],     s[2 * kp][3],     pa_hi[1], pa_lo[1]);
            split2(s[2 * kp + 1][0], s[2 * kp + 1][1], pa_hi[2], pa_lo[2]);
            split2(s[2 * kp + 1][2], s[2 * kp + 1][3], pa_hi[3], pa_lo[3]);
#pragma unroll
            for (int n2 = 0; n2 < 16; n2++) {
                uint32_t vb[2];
                uint32_t vo = v_off + (uint32_t)(kp * 16 * AP) * 2 + n2 * 16;
                ldm_x2_t(vb, sV_hi + vo);
                mma16816(o[n2], pa_hi, vb);
                mma16816(o[n2], pa_lo, vb);
                ldm_x2_t(vb, sV_lo + vo);
                mma16816(o[n2], pa_hi, vb);
            }
        }
        __syncthreads();   // stage st free for reuse
    }

    // ---- epilogue: normalize, split hi/lo, write O-proj A operand ----
    const float inv0 = 1.f / l0, inv1 = 1.f / l1;
    const int col0 = (lane & 3) * 2;
    const size_t base0 = (size_t)(b * Sq + r0) * Hh + nh * HDd;
    const size_t base1 = base0 + (size_t)8 * Hh;
#pragma unroll
    for (int n2 = 0; n2 < 16; n2++) {
        uint32_t hv, lv;
        split2(o[n2][0] * inv0, o[n2][1] * inv0, hv, lv);
        *(uint32_t*)(&g_ahi[base0 + n2 * 8 + col0]) = hv;
        *(uint32_t*)(&g_alo[base0 + n2 * 8 + col0]) = lv;
        split2(o[n2][2] * inv1, o[n2][3] * inv1, hv, lv);
        *(uint32_t*)(&g_ahi[base1 + n2 * 8 + col0]) = hv;
        *(uint32_t*)(&g_alo[base1 + n2 * 8 + col0]) = lv;
    }
}

// ============================================================================
// launch
// ============================================================================
extern "C" void kernel_launch(void* const* d_in, const int* in_sizes, int n_in,
                              void* d_out, int out_size) {
    const float* hidden = (const float*)d_in[0];
    const float* cosT   = (const float*)d_in[1];
    const float* sinT   = (const float*)d_in[2];
    // d_in[3] = attention_mask (causal; analytic)
    const float* w_qkv  = (const float*)d_in[4];
    const float* w_o    = (const float*)d_in[5];
    float* out = (float*)d_out;

    float* p_qkv;
    cudaGetSymbolAddress((void**)&p_qkv, g_qkv);

    __nv_bfloat16 *p_hhi, *p_hlo, *p_wqhi, *p_wqlo, *p_ahi, *p_alo, *p_wohi, *p_wolo;
    cudaGetSymbolAddress((void**)&p_hhi, g_hhi);
    cudaGetSymbolAddress((void**)&p_hlo, g_hlo);
    cudaGetSymbolAddress((void**)&p_wqhi, g_wqhi);
    cudaGetSymbolAddress((void**)&p_wqlo, g_wqlo);
    cudaGetSymbolAddress((void**)&p_ahi, g_ahi);
    cudaGetSymbolAddress((void**)&p_alo, g_alo);
    cudaGetSymbolAddress((void**)&p_wohi, g_wohi);
    cudaGetSymbolAddress((void**)&p_wolo, g_wolo);

    cudaFuncSetAttribute(gemm_mma, cudaFuncAttributeMaxDynamicSharedMemorySize, GEMM_SMEM);
    cudaFuncSetAttribute(fattn_mma, cudaFuncAttributeMaxDynamicSharedMemorySize, FA_SMEM);

    // 0) bf16 hi/lo splits
    split_hilo<<<(4096 * 2048 / 4 + 255) / 256, 256>>>(hidden, p_hhi, p_hlo, 4096 * 2048 / 4);
    split_hilo<<<(6144 * 2048 / 4 + 255) / 256, 256>>>(w_qkv, p_wqhi, p_wqlo, 6144 * 2048 / 4);
    split_hilo<<<(2048 * 2048 / 4 + 255) / 256, 256>>>(w_o, p_wohi, p_wolo, 2048 * 2048 / 4);

    // 1) QKV = hidden @ w_qkv^T
    gemm_mma<<<dim3(QKV_N / 128, M_ROWS / 128), 256, GEMM_SMEM>>>(
        p_hhi, p_hlo, p_wqhi, p_wqlo, p_qkv, M_ROWS, QKV_N, Hh);

    // 2) RoPE + split into bf16 hi/lo q/k/v
    rope_split<<<QKV_ELEMS / 256, 256>>>(cosT, sinT);

    // 3) tensor-core causal flash attention (writes g_ahi/g_alo directly)
    fattn_mma<<<dim3(Sq / 128, Bsz * NHd), 256, FA_SMEM>>>();

    // 4) out = attn @ w_o^T
    gemm_mma<<<dim3(Hh / 128, M_ROWS / 128), 256, GEMM_SMEM>>>(
        p_ahi, p_alo, p_wohi, p_wolo, out, M_ROWS, Hh, Hh);
}